// round 10
// baseline (speedup 1.0000x reference)
#include <cuda_runtime.h>
#include <math.h>

// Problem dims
#define TT   512
#define BB   256
#define OBSD 128
#define ACTD 32
#define IND  160
#define HIDD 512
#define G3D  1536
#define HFD  512

static constexpr size_t TBn = (size_t)TT * BB;      // 131072
static constexpr int NBLK = 2048;                    // reduction blocks per sum

// -------- scratch (static device globals; no runtime allocation) ----------
__device__ float g_GI [TBn * G3D];   // [T*B, 1536] input-gate preacts
__device__ float g_GI0[BB  * G3D];   // step-0 preacts
__device__ float g_HS [TBn * HIDD];  // emitted hidden states
__device__ float g_part[3 * NBLK];   // loss partials

// grid-barrier state (zero-init; counter returns to 0 every barrier).
__device__ unsigned g_rcnt;
__device__ unsigned g_rgen;

__device__ __forceinline__ float4 ldg4(const float* p) {
    return *reinterpret_cast<const float4*>(p);
}
__device__ __forceinline__ float sigmoidf_(float x) { return 1.f / (1.f + expf(-x)); }

// ---- packed fp32x2 helpers (sm_100+ PTX; ptxas never emits these itself) ----
__device__ __forceinline__ unsigned long long pk2(float lo, float hi) {
    unsigned long long r;
    asm("mov.b64 %0, {%1, %2};" : "=l"(r) : "f"(lo), "f"(hi));
    return r;
}
__device__ __forceinline__ void fma2(unsigned long long& d,
                                     unsigned long long a, unsigned long long b) {
    asm("fma.rn.f32x2 %0, %1, %2, %0;" : "+l"(d) : "l"(a), "l"(b));
}
__device__ __forceinline__ float2 upk2(unsigned long long v) {
    float2 f;
    asm("mov.b64 {%0, %1}, %2;" : "=f"(f.x), "=f"(f.y) : "l"(v));
    return f;
}

// ---------------------------------------------------------------------------
// Generic tiled SGEMM with f32x2 inner loop (unchanged from R8 — measured at
// the fp32 roofline):  C[M,N] = act( A[M,K] @ W[N,K]^T + bias[N] )
// ---------------------------------------------------------------------------
template<int BM, int BN, int BK, int TM, int TN, int ACTMODE, bool CONCAT>
__global__ void __launch_bounds__((BM / TM) * (BN / TN))
sgemm_k(const float* __restrict__ A, int ldA,
        const float* __restrict__ A2,
        const float* __restrict__ W, int ldW,
        const float* __restrict__ bias,
        float* __restrict__ C, int ldC,
        int K)
{
    constexpr int NT = (BM / TM) * (BN / TN);
    constexpr int KQ = BK / 4;
    constexpr int TNP = TN / 2;

    __shared__ __align__(16) float As[BK][BM + 4];
    __shared__ __align__(16) float Ws[BK][BN + 4];

    const int tid = threadIdx.x;
    const int tx  = tid % (BN / TN);
    const int ty  = tid / (BN / TN);
    const int m0  = blockIdx.y * BM;
    const int n0  = blockIdx.x * BN;

    unsigned long long acc2[TM][TNP];
#pragma unroll
    for (int i = 0; i < TM; i++)
#pragma unroll
        for (int j = 0; j < TNP; j++) acc2[i][j] = 0ull;

    for (int k0 = 0; k0 < K; k0 += BK) {
        for (int i4 = tid; i4 < BM * KQ; i4 += NT) {
            int m = i4 / KQ, q = i4 % KQ;
            int kg = k0 + q * 4;
            float4 v;
            if (CONCAT) {
                if (kg < OBSD) v = ldg4(A  + (size_t)(m0 + m) * OBSD + kg);
                else           v = ldg4(A2 + (size_t)(m0 + m) * ACTD + (kg - OBSD));
            } else {
                v = ldg4(A + (size_t)(m0 + m) * ldA + kg);
            }
            As[q * 4 + 0][m] = v.x; As[q * 4 + 1][m] = v.y;
            As[q * 4 + 2][m] = v.z; As[q * 4 + 3][m] = v.w;
        }
        for (int i4 = tid; i4 < BN * KQ; i4 += NT) {
            int n = i4 / KQ, q = i4 % KQ;
            int kg = k0 + q * 4;
            float4 v = ldg4(W + (size_t)(n0 + n) * ldW + kg);
            Ws[q * 4 + 0][n] = v.x; Ws[q * 4 + 1][n] = v.y;
            Ws[q * 4 + 2][n] = v.z; Ws[q * 4 + 3][n] = v.w;
        }
        __syncthreads();

#pragma unroll
        for (int kk = 0; kk < BK; kk++) {
            float a[TM];
#pragma unroll
            for (int i = 0; i < TM; i += 4)
                *reinterpret_cast<float4*>(&a[i]) =
                    *reinterpret_cast<const float4*>(&As[kk][ty * TM + i]);
            unsigned long long b2[TNP];
#pragma unroll
            for (int j = 0; j < TNP; j += 2) {
                ulonglong2 t = *reinterpret_cast<const ulonglong2*>(&Ws[kk][tx * TN + 2 * j]);
                b2[j] = t.x; b2[j + 1] = t.y;
            }
#pragma unroll
            for (int i = 0; i < TM; i++) {
                unsigned long long ad = pk2(a[i], a[i]);
#pragma unroll
                for (int j = 0; j < TNP; j++) fma2(acc2[i][j], ad, b2[j]);
            }
        }
        __syncthreads();
    }

#pragma unroll
    for (int i = 0; i < TM; i++) {
        size_t m = (size_t)m0 + ty * TM + i;
#pragma unroll
        for (int j = 0; j < TNP; j++) {
            float2 v2 = upk2(acc2[i][j]);
            int n = n0 + tx * TN + 2 * j;
            float v = v2.x + bias[n];
            float w = v2.y + bias[n + 1];
            if (ACTMODE == 1) {
                v = (v > 0.f) ? v : expm1f(v);
                w = (w > 0.f) ? w : expm1f(w);
            }
            C[m * (size_t)ldC + n]     = v;
            C[m * (size_t)ldC + n + 1] = w;
        }
    }
}

// ---------------------------------------------------------------------------
// Persistent GRU recurrence v2: 256 CTAs (2/SM), 256 threads each.
//   CTA slice: 32 batch rows x 16 gate cols.  W slice (3 x 16 x 512 = 96KB)
//   stays in smem for the whole kernel; h_t staged in double-buffered 32-k
//   chunks.  Per thread: 1 row x 2 cols x 3 gates -> per kk: 1 scalar LDS
//   (broadcast) + 3 LDS.64 + 1 mov + 3 FFMA2.  gi/hp for the gate epilogue
//   prefetched into registers BEFORE the k-loop.
// ---------------------------------------------------------------------------
#define RNCTA 256
#define RJC   16            // gate cols per CTA
#define RBR   32            // batch rows per CTA
#define RCHK  32            // K chunk
#define RAS   36            // A chunk row stride (32 + 4: aligned, conflict-free)

__device__ __forceinline__ void rnn_load_chunk(float* __restrict__ dst,
                                               const float* __restrict__ hp,
                                               int b0, int c, int tid)
{
    int row = tid >> 3, q = tid & 7;            // 32 rows x 8 float4 = 256 loads
    float4 v = ldg4(hp + (size_t)(b0 + row) * HIDD + c * RCHK + q * 4);
    *reinterpret_cast<float4*>(&dst[row * RAS + q * 4]) = v;
}

__global__ void __launch_bounds__(256, 2)
rnn_k(const float* __restrict__ w_hh, const float* __restrict__ b_hh,
      const float* __restrict__ gi_all, float* __restrict__ hs)
{
    extern __shared__ float sm[];
    float* Wsm = sm;                         // 3*512*16 = 24576 floats (96KB)
    float* A0  = sm + 3 * 512 * RJC;         // 32*36 floats
    float* A1  = A0 + RBR * RAS;

    const int tid = threadIdx.x;
    const int cg  = blockIdx.x & 31;         // 32 col groups x 16 cols = 512
    const int bg  = blockIdx.x >> 5;         // 8 batch groups x 32 rows = 256
    const int j0  = cg * RJC;
    const int b0  = bg * RBR;
    const int tx  = tid & 7;                 // 8 col-pairs (16 cols)
    const int ty  = tid >> 3;                // 32 rows, one per ty

    // one-time: load this CTA's w_hh slice into smem as [g][k][col], stride 16
    for (int i4 = tid; i4 < 48 * 128; i4 += 256) {
        int r = i4 >> 7, q = i4 & 127;
        int g = r >> 4, col = r & 15;
        float4 v = ldg4(w_hh + (size_t)(g * HIDD + j0 + col) * HIDD + q * 4);
        Wsm[(g * 512 + q * 4 + 0) * RJC + col] = v.x;
        Wsm[(g * 512 + q * 4 + 1) * RJC + col] = v.y;
        Wsm[(g * 512 + q * 4 + 2) * RJC + col] = v.z;
        Wsm[(g * 512 + q * 4 + 3) * RJC + col] = v.w;
    }
    const int m  = b0 + ty;
    const int jg = j0 + 2 * tx;
    const float2 br = *reinterpret_cast<const float2*>(b_hh + jg);
    const float2 bz = *reinterpret_cast<const float2*>(b_hh + 512 + jg);
    const float2 bn = *reinterpret_cast<const float2*>(b_hh + 1024 + jg);
    __syncthreads();

    for (int t = 0; t < TT - 1; t++) {
        const float* hp = hs + (size_t)t * BB * HIDD;
        float*       ho = hs + (size_t)(t + 1) * BB * HIDD;
        const float* gim = gi_all + (size_t)t * BB * G3D + (size_t)m * G3D;

        // prefetch epilogue operands (DRAM latency hides under the k-loop)
        float2 gir = *reinterpret_cast<const float2*>(gim + jg);
        float2 giz = *reinterpret_cast<const float2*>(gim + 512 + jg);
        float2 gin = *reinterpret_cast<const float2*>(gim + 1024 + jg);
        float2 hpv = *reinterpret_cast<const float2*>(hp + (size_t)m * HIDD + jg);

        unsigned long long ar2 = 0ull, az2 = 0ull, an2 = 0ull;

        rnn_load_chunk(A0, hp, b0, 0, tid);
        __syncthreads();
#pragma unroll 1
        for (int c = 0; c < 16; c++) {
            const float* Ac = (c & 1) ? A1 : A0;
            if (c < 15) rnn_load_chunk((c & 1) ? A0 : A1, hp, b0, c + 1, tid);
            const float* wbase = &Wsm[c * RCHK * RJC + 2 * tx];
            const float* abase = &Ac[ty * RAS];
#pragma unroll
            for (int kk = 0; kk < RCHK; kk++) {
                float a = abase[kk];
                unsigned long long ad = pk2(a, a);
                unsigned long long wr2 = *reinterpret_cast<const unsigned long long*>(
                    wbase + kk * RJC);
                unsigned long long wz2 = *reinterpret_cast<const unsigned long long*>(
                    wbase + (512 + kk) * RJC);
                unsigned long long wn2 = *reinterpret_cast<const unsigned long long*>(
                    wbase + (1024 + kk) * RJC);
                fma2(ar2, ad, wr2);
                fma2(az2, ad, wz2);
                fma2(an2, ad, wn2);
            }
            __syncthreads();
        }

        // gate math + store this thread's 2 cols of h_{t+1}
        {
            float2 vr = upk2(ar2), vz = upk2(az2), vn = upk2(an2);
            float r0 = sigmoidf_(gir.x + vr.x + br.x);
            float r1 = sigmoidf_(gir.y + vr.y + br.y);
            float z0 = sigmoidf_(giz.x + vz.x + bz.x);
            float z1 = sigmoidf_(giz.y + vz.y + bz.y);
            float n0 = tanhf    (gin.x + r0 * (vn.x + bn.x));
            float n1 = tanhf    (gin.y + r1 * (vn.y + bn.y));
            float2 hv;
            hv.x = (1.f - z0) * n0 + z0 * hpv.x;
            hv.y = (1.f - z1) * n1 + z1 * hpv.y;
            *reinterpret_cast<float2*>(ho + (size_t)m * HIDD + jg) = hv;
        }

        // ---- grid barrier (generation-counting; all 256 CTAs resident) ----
        __threadfence();
        __syncthreads();
        if (tid == 0) {
            unsigned g = *(volatile unsigned*)&g_rgen;
            __threadfence();
            unsigned a = atomicAdd(&g_rcnt, 1u);
            if (a == RNCTA - 1) {
                atomicExch(&g_rcnt, 0u);
                __threadfence();
                *(volatile unsigned*)&g_rgen = g + 1;
            } else {
                while (*(volatile unsigned*)&g_rgen == g) __nanosleep(32);
            }
        }
        __syncthreads();
    }
}

// step 0: h_prev = 0  =>  gh = b_hh,  h0 = (1-z)*n
__global__ void gate0_k(const float* __restrict__ gi, const float* __restrict__ bhh,
                        float* __restrict__ ho)
{
    int idx = blockIdx.x * blockDim.x + threadIdx.x;
    int b = idx >> 9, j = idx & 511;
    size_t base = (size_t)b * G3D + j;
    float r = sigmoidf_(gi[base]        + bhh[j]);
    float z = sigmoidf_(gi[base + 512]  + bhh[512 + j]);
    float n = tanhf    (gi[base + 1024] + r * bhh[1024 + j]);
    ho[idx] = (1.f - z) * n;
}

// ---------------------------------------------------------------------------
// N=1 head: pre_reward[m] = dot(F2[m,:], rw2) + rb2.  One warp per row.
// ---------------------------------------------------------------------------
__global__ void dot_k(const float* __restrict__ A, const float* __restrict__ w,
                      const float* __restrict__ bp, float* __restrict__ out)
{
    int g = blockIdx.x * blockDim.x + threadIdx.x;
    int row = g >> 5, lane = g & 31;
    const float4* a4 = reinterpret_cast<const float4*>(A + (size_t)row * HFD);
    const float4* w4 = reinterpret_cast<const float4*>(w);
    float s = 0.f;
#pragma unroll
    for (int i = lane; i < HFD / 4; i += 32) {
        float4 a = a4[i], b = w4[i];
        s += a.x * b.x + a.y * b.y + a.z * b.z + a.w * b.w;
    }
#pragma unroll
    for (int o = 16; o; o >>= 1) s += __shfl_xor_sync(0xffffffffu, s, o);
    if (lane == 0) out[row] = s + bp[0];
}

// ---------------------------------------------------------------------------
// Loss: deterministic 2-stage sum of squared residuals.
// ---------------------------------------------------------------------------
template<bool BCAST>
__global__ void reduce_sq_k(const float* __restrict__ x, const float* __restrict__ mu,
                            size_t n, float* __restrict__ part)
{
    float s = 0.f;
    for (size_t i = (size_t)blockIdx.x * blockDim.x + threadIdx.x; i < n;
         i += (size_t)gridDim.x * blockDim.x) {
        float m = BCAST ? mu[i >> 5] : mu[i];
        float d = x[i] - m;
        s += d * d;
    }
    __shared__ float sm[256];
    sm[threadIdx.x] = s; __syncthreads();
    for (int o = 128; o; o >>= 1) {
        if (threadIdx.x < o) sm[threadIdx.x] += sm[threadIdx.x + o];
        __syncthreads();
    }
    if (threadIdx.x == 0) part[blockIdx.x] = sm[0];
}

__global__ void finalize_k(const float* __restrict__ part, float* __restrict__ out)
{
    __shared__ double sm[256];
    double s = 0.0;
    for (int i = threadIdx.x; i < 3 * NBLK; i += 256) s += (double)part[i];
    sm[threadIdx.x] = s; __syncthreads();
    for (int o = 128; o; o >>= 1) {
        if (threadIdx.x < o) sm[threadIdx.x] += sm[threadIdx.x + o];
        __syncthreads();
    }
    if (threadIdx.x == 0) {
        const double LOG2PI = 1.8378770664093453;
        out[0] = (float)(0.5 * sm[0] / (double)(TT * BB)
                         + 0.5 * LOG2PI * (double)(OBSD + 2 * ACTD));
    }
}

// ---------------------------------------------------------------------------
extern "C" void kernel_launch(void* const* d_in, const int* in_sizes, int n_in,
                              void* d_out, int out_size)
{
    const float* obs    = (const float*)d_in[0];
    const float* action = (const float*)d_in[1];
    /* d_in[2] reward: unused by the reference math */
    const float* w_ih = (const float*)d_in[3];
    const float* w_hh = (const float*)d_in[4];
    const float* b_ih = (const float*)d_in[5];
    const float* b_hh = (const float*)d_in[6];
    const float* ow0 = (const float*)d_in[7],  *ob0 = (const float*)d_in[8];
    const float* ow1 = (const float*)d_in[9],  *ob1 = (const float*)d_in[10];
    const float* ow2 = (const float*)d_in[11], *ob2 = (const float*)d_in[12];
    const float* aw0 = (const float*)d_in[13], *ab0 = (const float*)d_in[14];
    const float* aw1 = (const float*)d_in[15], *ab1 = (const float*)d_in[16];
    const float* aw2 = (const float*)d_in[17], *ab2 = (const float*)d_in[18];
    const float* rw0 = (const float*)d_in[19], *rb0 = (const float*)d_in[20];
    const float* rw1 = (const float*)d_in[21], *rb1 = (const float*)d_in[22];
    const float* rw2 = (const float*)d_in[23], *rb2 = (const float*)d_in[24];

    float *GI, *GI0, *HS, *PART;
    cudaGetSymbolAddress((void**)&GI,   g_GI);
    cudaGetSymbolAddress((void**)&GI0,  g_GI0);
    cudaGetSymbolAddress((void**)&HS,   g_HS);
    cudaGetSymbolAddress((void**)&PART, g_part);
    // MLP scratch aliases the (dead after the recurrence) GI buffer.
    float* F1 = GI;
    float* F2 = GI + TBn * HFD;

    float* out      = (float*)d_out;
    float* pre_obs  = out + 1;
    float* pre_act  = pre_obs + TBn * OBSD;
    float* pre_rew  = pre_act + TBn * ACTD;

    // persistent kernel dynamic smem: 96KB W + 2 x A chunk
    const int rnn_smem = (3 * 512 * RJC + 2 * RBR * RAS) * (int)sizeof(float);
    cudaFuncSetAttribute(rnn_k, cudaFuncAttributeMaxDynamicSharedMemorySize, rnn_smem);

    // 1) GI = [obs‖action] @ w_ih^T + b_ih   for all T*B rows
    sgemm_k<128, 128, 8, 8, 8, 0, true><<<dim3(G3D / 128, TBn / 128), 256>>>(
        obs, 0, action, w_ih, IND, b_ih, GI, G3D, IND);

    // 2) GI0 = obs[0] @ w_ih[:, :128]^T + b_ih  (action part of x0 is zero)
    sgemm_k<64, 64, 8, 4, 4, 0, false><<<dim3(G3D / 64, BB / 64), 256>>>(
        obs, OBSD, nullptr, w_ih, IND, b_ih, GI0, G3D, OBSD);

    // 3) h0 (gh == b_hh since h_prev == 0) -> HS[0]
    gate0_k<<<(BB * HIDD) / 256, 256>>>(GI0, b_hh, HS);

    // 4) recurrence: ONE persistent kernel, 256 CTAs (2/SM), all 511 steps
    rnn_k<<<RNCTA, 256, rnn_smem>>>(w_hh, b_hh, GI, HS);

    dim3 gH(HFD / 128, TBn / 128);
    dim3 gO(OBSD / 128, TBn / 128);
    dim3 gA(ACTD / 32, TBn / 128);

    // 5) obs head
    sgemm_k<128, 128, 8, 8, 8, 1, false><<<gH, 256>>>(HS, HIDD, nullptr, ow0, HIDD, ob0, F1, HFD, HIDD);
    sgemm_k<128, 128, 8, 8, 8, 1, false><<<gH, 256>>>(F1, HFD, nullptr, ow1, HFD, ob1, F2, HFD, HFD);
    sgemm_k<128, 128, 8, 8, 8, 0, false><<<gO, 256>>>(F2, HFD, nullptr, ow2, HFD, ob2, pre_obs, OBSD, HFD);

    // 6) action head (stop_gradient is identity in forward)
    sgemm_k<128, 128, 8, 8, 8, 1, false><<<gH, 256>>>(HS, HIDD, nullptr, aw0, HIDD, ab0, F1, HFD, HIDD);
    sgemm_k<128, 128, 8, 8, 8, 1, false><<<gH, 256>>>(F1, HFD, nullptr, aw1, HFD, ab1, F2, HFD, HFD);
    sgemm_k<128, 32, 8, 8, 4, 0, false><<<gA, 128>>>(F2, HFD, nullptr, aw2, HFD, ab2, pre_act, ACTD, HFD);

    // 7) reward head
    sgemm_k<128, 128, 8, 8, 8, 1, false><<<gH, 256>>>(HS, HIDD, nullptr, rw0, HIDD, rb0, F1, HFD, HIDD);
    sgemm_k<128, 128, 8, 8, 8, 1, false><<<gH, 256>>>(F1, HFD, nullptr, rw1, HFD, rb1, F2, HFD, HFD);
    dot_k<<<TBn / 8, 256>>>(F2, rw2, rb2, pre_rew);

    // 8) losses (reward_loss faithfully reproduces the broadcast-vs-action bug)
    reduce_sq_k<false><<<NBLK, 256>>>(obs,    pre_obs, TBn * OBSD, PART);
    reduce_sq_k<false><<<NBLK, 256>>>(action, pre_act, TBn * ACTD, PART + NBLK);
    reduce_sq_k<true ><<<NBLK, 256>>>(action, pre_rew, TBn * ACTD, PART + 2 * NBLK);
    finalize_k<<<1, 256>>>(PART, out);
}

// round 11
// speedup vs baseline: 1.4276x; 1.4276x over previous
#include <cuda_runtime.h>
#include <math.h>

// Problem dims
#define TT   512
#define BB   256
#define OBSD 128
#define ACTD 32
#define IND  160
#define HIDD 512
#define G3D  1536
#define HFD  512

static constexpr size_t TBn = (size_t)TT * BB;      // 131072
static constexpr int NBLK = 2048;                    // reduction blocks per sum

// -------- scratch (static device globals; no runtime allocation) ----------
__device__ float g_GI [TBn * G3D];   // [T*B, 1536] input-gate preacts
__device__ float g_GI0[BB  * G3D];   // step-0 preacts
__device__ float g_HS [TBn * HIDD];  // emitted hidden states
__device__ float g_P0 [BB * G3D];    // K-half-0 partial preacts [256,1536]
__device__ float g_P1 [BB * G3D];    // K-half-1 partial preacts
__device__ float g_part[3 * NBLK];   // loss partials

// monotonic sync counters (zeroed by gate0_k each call -> graph-replay safe)
__device__ unsigned g_pcnt[64];      // per-slice pair counters
__device__ unsigned g_bcnt[4];       // per-bg-group barrier counters

__device__ __forceinline__ float4 ldg4(const float* p) {
    return *reinterpret_cast<const float4*>(p);
}
__device__ __forceinline__ float sigmoidf_(float x) { return 1.f / (1.f + expf(-x)); }

// ---- packed fp32x2 helpers ----
__device__ __forceinline__ unsigned long long pk2(float lo, float hi) {
    unsigned long long r;
    asm("mov.b64 %0, {%1, %2};" : "=l"(r) : "f"(lo), "f"(hi));
    return r;
}
__device__ __forceinline__ void fma2(unsigned long long& d,
                                     unsigned long long a, unsigned long long b) {
    asm("fma.rn.f32x2 %0, %1, %2, %0;" : "+l"(d) : "l"(a), "l"(b));
}
__device__ __forceinline__ float2 upk2(unsigned long long v) {
    float2 f;
    asm("mov.b64 {%0, %1}, %2;" : "=f"(f.x), "=f"(f.y) : "l"(v));
    return f;
}

// ---------------------------------------------------------------------------
// Generic tiled SGEMM with f32x2 inner loop (measured at the fp32 roofline).
// ---------------------------------------------------------------------------
template<int BM, int BN, int BK, int TM, int TN, int ACTMODE, bool CONCAT>
__global__ void __launch_bounds__((BM / TM) * (BN / TN))
sgemm_k(const float* __restrict__ A, int ldA,
        const float* __restrict__ A2,
        const float* __restrict__ W, int ldW,
        const float* __restrict__ bias,
        float* __restrict__ C, int ldC,
        int K)
{
    constexpr int NT = (BM / TM) * (BN / TN);
    constexpr int KQ = BK / 4;
    constexpr int TNP = TN / 2;

    __shared__ __align__(16) float As[BK][BM + 4];
    __shared__ __align__(16) float Ws[BK][BN + 4];

    const int tid = threadIdx.x;
    const int tx  = tid % (BN / TN);
    const int ty  = tid / (BN / TN);
    const int m0  = blockIdx.y * BM;
    const int n0  = blockIdx.x * BN;

    unsigned long long acc2[TM][TNP];
#pragma unroll
    for (int i = 0; i < TM; i++)
#pragma unroll
        for (int j = 0; j < TNP; j++) acc2[i][j] = 0ull;

    for (int k0 = 0; k0 < K; k0 += BK) {
        for (int i4 = tid; i4 < BM * KQ; i4 += NT) {
            int m = i4 / KQ, q = i4 % KQ;
            int kg = k0 + q * 4;
            float4 v;
            if (CONCAT) {
                if (kg < OBSD) v = ldg4(A  + (size_t)(m0 + m) * OBSD + kg);
                else           v = ldg4(A2 + (size_t)(m0 + m) * ACTD + (kg - OBSD));
            } else {
                v = ldg4(A + (size_t)(m0 + m) * ldA + kg);
            }
            As[q * 4 + 0][m] = v.x; As[q * 4 + 1][m] = v.y;
            As[q * 4 + 2][m] = v.z; As[q * 4 + 3][m] = v.w;
        }
        for (int i4 = tid; i4 < BN * KQ; i4 += NT) {
            int n = i4 / KQ, q = i4 % KQ;
            int kg = k0 + q * 4;
            float4 v = ldg4(W + (size_t)(n0 + n) * ldW + kg);
            Ws[q * 4 + 0][n] = v.x; Ws[q * 4 + 1][n] = v.y;
            Ws[q * 4 + 2][n] = v.z; Ws[q * 4 + 3][n] = v.w;
        }
        __syncthreads();

#pragma unroll
        for (int kk = 0; kk < BK; kk++) {
            float a[TM];
#pragma unroll
            for (int i = 0; i < TM; i += 4)
                *reinterpret_cast<float4*>(&a[i]) =
                    *reinterpret_cast<const float4*>(&As[kk][ty * TM + i]);
            unsigned long long b2[TNP];
#pragma unroll
            for (int j = 0; j < TNP; j += 2) {
                ulonglong2 t = *reinterpret_cast<const ulonglong2*>(&Ws[kk][tx * TN + 2 * j]);
                b2[j] = t.x; b2[j + 1] = t.y;
            }
#pragma unroll
            for (int i = 0; i < TM; i++) {
                unsigned long long ad = pk2(a[i], a[i]);
#pragma unroll
                for (int j = 0; j < TNP; j++) fma2(acc2[i][j], ad, b2[j]);
            }
        }
        __syncthreads();
    }

#pragma unroll
    for (int i = 0; i < TM; i++) {
        size_t m = (size_t)m0 + ty * TM + i;
#pragma unroll
        for (int j = 0; j < TNP; j++) {
            float2 v2 = upk2(acc2[i][j]);
            int n = n0 + tx * TN + 2 * j;
            float v = v2.x + bias[n];
            float w = v2.y + bias[n + 1];
            if (ACTMODE == 1) {
                v = (v > 0.f) ? v : expm1f(v);
                w = (w > 0.f) ? w : expm1f(w);
            }
            C[m * (size_t)ldC + n]     = v;
            C[m * (size_t)ldC + n + 1] = w;
        }
    }
}

// ---------------------------------------------------------------------------
// Persistent GRU recurrence v3: K-split for fat threads on a full grid.
// 128 CTAs x 256 threads.  CTA i: slice s=i>>1 (bg=s>>4: 64 rows, cg=s&15:
// 32 cols), K-half kh=i&1 (K=256).  W slice (3x32x256 = 96KB) in smem for
// the whole kernel; A chunks (32k x 64 rows, k-major) double-buffered.
// Thread: 4 rows x 2 cols x 3 gates = 12 FFMA2 per (1 LDS.128 + 3 LDS.64).
// Per step: GEMM -> partials to P[kh] -> pair sync -> fused gates (pair
// splits slice rows) -> per-bg barrier (32 CTAs).
// ---------------------------------------------------------------------------
#define RNCTA 128

__device__ __forceinline__ void rnn_load_chunk(float* __restrict__ dst,
                                               const float* __restrict__ hp,
                                               int b0, int kb, int c, int tid)
{
#pragma unroll
    for (int p = 0; p < 2; p++) {
        int u = p * 256 + tid;
        int row = u & 63, q = u >> 6;                 // 64 rows x 8 float4
        float4 v = ldg4(hp + (size_t)(b0 + row) * HIDD + kb + c * 32 + q * 4);
        dst[(q * 4 + 0) * 64 + row] = v.x;
        dst[(q * 4 + 1) * 64 + row] = v.y;
        dst[(q * 4 + 2) * 64 + row] = v.z;
        dst[(q * 4 + 3) * 64 + row] = v.w;
    }
}

__global__ void __launch_bounds__(256)
rnn_k(const float* __restrict__ w_hh, const float* __restrict__ b_hh,
      const float* __restrict__ gi_all, float* __restrict__ hs,
      float* __restrict__ P0, float* __restrict__ P1)
{
    extern __shared__ float sm[];
    float* Wsm = sm;                     // [3][256][32] = 24576 floats (96KB)
    float* Abuf = sm + 3 * 256 * 32;     // 2 x [32][64] = 4096 floats (16KB)

    const int tid   = threadIdx.x;
    const int slice = blockIdx.x >> 1;
    const int kh    = blockIdx.x & 1;
    const int bg    = slice >> 4;        // 4 groups of 64 rows
    const int cg    = slice & 15;        // 16 groups of 32 cols
    const int b0    = bg * 64;
    const int j0    = cg * 32;
    const int kb    = kh * 256;
    const int tx    = tid & 15;          // 16 col-pairs
    const int ty    = tid >> 4;          // 16 row-quads
    float* Pm = kh ? P1 : P0;

    // one-time: W slice -> smem as [g][k][col], k-major
    for (int i4 = tid; i4 < 3 * 32 * 64; i4 += 256) {
        int g = i4 >> 11;
        int r = i4 & 2047;
        int col = r >> 6;                // 0..31
        int kq  = r & 63;                // k = 4*kq
        float4 v = ldg4(w_hh + (size_t)(g * HIDD + j0 + col) * HIDD + kb + kq * 4);
        Wsm[(g * 256 + kq * 4 + 0) * 32 + col] = v.x;
        Wsm[(g * 256 + kq * 4 + 1) * 32 + col] = v.y;
        Wsm[(g * 256 + kq * 4 + 2) * 32 + col] = v.z;
        Wsm[(g * 256 + kq * 4 + 3) * 32 + col] = v.w;
    }

    // gate-phase thread mapping (32 rows x 32 cols per CTA)
    const int gr   = tid >> 3;               // 0..31
    const int gc   = (tid & 7) * 4;          // col group of 4
    const int grow = b0 + kh * 32 + gr;
    const int gcol = j0 + gc;
    const float4 bhr = ldg4(b_hh + gcol);
    const float4 bhz = ldg4(b_hh + 512 + gcol);
    const float4 bhn = ldg4(b_hh + 1024 + gcol);
    __syncthreads();

    for (int t = 0; t < TT - 1; t++) {
        const float* hp = hs + (size_t)t * BB * HIDD;
        float*       ho = hs + (size_t)(t + 1) * BB * HIDD;
        const float* gi = gi_all + (size_t)t * BB * G3D;

        // prefetch gate-phase operands (t-indexed addresses: never stale)
        const float* gim = gi + (size_t)grow * G3D;
        float4 gvr = ldg4(gim + gcol);
        float4 gvz = ldg4(gim + 512 + gcol);
        float4 gvn = ldg4(gim + 1024 + gcol);
        float4 hp4 = ldg4(hp + (size_t)grow * HIDD + gcol);

        unsigned long long aR[4] = {0,0,0,0}, aZ[4] = {0,0,0,0}, aN[4] = {0,0,0,0};

        rnn_load_chunk(Abuf, hp, b0, kb, 0, tid);
        __syncthreads();
#pragma unroll 1
        for (int c = 0; c < 8; c++) {
            const float* Ac = Abuf + (c & 1) * 2048;
            if (c < 7) rnn_load_chunk(Abuf + ((c + 1) & 1) * 2048, hp, b0, kb, c + 1, tid);
            const float* wR = &Wsm[(0 * 256 + c * 32) * 32 + 2 * tx];
            const float* wZ = &Wsm[(1 * 256 + c * 32) * 32 + 2 * tx];
            const float* wN = &Wsm[(2 * 256 + c * 32) * 32 + 2 * tx];
#pragma unroll
            for (int kk = 0; kk < 32; kk++) {
                float4 a4 = *reinterpret_cast<const float4*>(&Ac[kk * 64 + 4 * ty]);
                unsigned long long r2 = *reinterpret_cast<const unsigned long long*>(wR + kk * 32);
                unsigned long long z2 = *reinterpret_cast<const unsigned long long*>(wZ + kk * 32);
                unsigned long long n2 = *reinterpret_cast<const unsigned long long*>(wN + kk * 32);
                unsigned long long a0 = pk2(a4.x, a4.x);
                unsigned long long a1 = pk2(a4.y, a4.y);
                unsigned long long a2 = pk2(a4.z, a4.z);
                unsigned long long a3 = pk2(a4.w, a4.w);
                fma2(aR[0], a0, r2); fma2(aR[1], a1, r2);
                fma2(aR[2], a2, r2); fma2(aR[3], a3, r2);
                fma2(aZ[0], a0, z2); fma2(aZ[1], a1, z2);
                fma2(aZ[2], a2, z2); fma2(aZ[3], a3, z2);
                fma2(aN[0], a0, n2); fma2(aN[1], a1, n2);
                fma2(aN[2], a2, n2); fma2(aN[3], a3, n2);
            }
            __syncthreads();
        }

        // write partial preacts for this K-half
#pragma unroll
        for (int i = 0; i < 4; i++) {
            size_t row = (size_t)(b0 + 4 * ty + i);
            float2 vr = upk2(aR[i]), vz = upk2(aZ[i]), vn = upk2(aN[i]);
            *reinterpret_cast<float2*>(&Pm[row * G3D + j0 + 2 * tx])        = vr;
            *reinterpret_cast<float2*>(&Pm[row * G3D + 512 + j0 + 2 * tx])  = vz;
            *reinterpret_cast<float2*>(&Pm[row * G3D + 1024 + j0 + 2 * tx]) = vn;
        }

        // ---- pair sync: wait for the partner K-half ----
        __threadfence();
        __syncthreads();
        if (tid == 0) {
            atomicAdd(&g_pcnt[slice], 1u);
            while (((volatile unsigned*)g_pcnt)[slice] < 2u * (unsigned)(t + 1))
                __nanosleep(20);
        }
        __syncthreads();

        // ---- fused gates on this CTA's 32 rows x 32 cols (L2-only P reads) ----
        {
            size_t pb = (size_t)grow * G3D + gcol;
            float4 p0r = __ldcg(reinterpret_cast<const float4*>(P0 + pb));
            float4 p1r = __ldcg(reinterpret_cast<const float4*>(P1 + pb));
            float4 p0z = __ldcg(reinterpret_cast<const float4*>(P0 + pb + 512));
            float4 p1z = __ldcg(reinterpret_cast<const float4*>(P1 + pb + 512));
            float4 p0n = __ldcg(reinterpret_cast<const float4*>(P0 + pb + 1024));
            float4 p1n = __ldcg(reinterpret_cast<const float4*>(P1 + pb + 1024));
            float4 o;
            {
                float r = sigmoidf_(gvr.x + p0r.x + p1r.x + bhr.x);
                float z = sigmoidf_(gvz.x + p0z.x + p1z.x + bhz.x);
                float n = tanhf    (gvn.x + r * (p0n.x + p1n.x + bhn.x));
                o.x = (1.f - z) * n + z * hp4.x;
            }
            {
                float r = sigmoidf_(gvr.y + p0r.y + p1r.y + bhr.y);
                float z = sigmoidf_(gvz.y + p0z.y + p1z.y + bhz.y);
                float n = tanhf    (gvn.y + r * (p0n.y + p1n.y + bhn.y));
                o.y = (1.f - z) * n + z * hp4.y;
            }
            {
                float r = sigmoidf_(gvr.z + p0r.z + p1r.z + bhr.z);
                float z = sigmoidf_(gvz.z + p0z.z + p1z.z + bhz.z);
                float n = tanhf    (gvn.z + r * (p0n.z + p1n.z + bhn.z));
                o.z = (1.f - z) * n + z * hp4.z;
            }
            {
                float r = sigmoidf_(gvr.w + p0r.w + p1r.w + bhr.w);
                float z = sigmoidf_(gvz.w + p0z.w + p1z.w + bhz.w);
                float n = tanhf    (gvn.w + r * (p0n.w + p1n.w + bhn.w));
                o.w = (1.f - z) * n + z * hp4.w;
            }
            *reinterpret_cast<float4*>(ho + (size_t)grow * HIDD + gcol) = o;
        }

        // ---- per-bg barrier (32 CTAs sharing these 64 batch rows) ----
        __threadfence();
        __syncthreads();
        if (tid == 0) {
            atomicAdd(&g_bcnt[bg], 1u);
            while (((volatile unsigned*)g_bcnt)[bg] < 32u * (unsigned)(t + 1))
                __nanosleep(20);
        }
        __syncthreads();
    }
}

// step 0: h_prev = 0  =>  gh = b_hh,  h0 = (1-z)*n.  Also zeroes the rnn
// sync counters (runs before rnn_k every call -> graph-replay safe).
__global__ void gate0_k(const float* __restrict__ gi, const float* __restrict__ bhh,
                        float* __restrict__ ho)
{
    if (blockIdx.x == 0 && threadIdx.x == 0) {
        for (int i = 0; i < 64; i++) g_pcnt[i] = 0u;
        for (int i = 0; i < 4;  i++) g_bcnt[i] = 0u;
        __threadfence();
    }
    int idx = blockIdx.x * blockDim.x + threadIdx.x;
    int b = idx >> 9, j = idx & 511;
    size_t base = (size_t)b * G3D + j;
    float r = sigmoidf_(gi[base]        + bhh[j]);
    float z = sigmoidf_(gi[base + 512]  + bhh[512 + j]);
    float n = tanhf    (gi[base + 1024] + r * bhh[1024 + j]);
    ho[idx] = (1.f - z) * n;
}

// ---------------------------------------------------------------------------
// N=1 head: one warp per row.
// ---------------------------------------------------------------------------
__global__ void dot_k(const float* __restrict__ A, const float* __restrict__ w,
                      const float* __restrict__ bp, float* __restrict__ out)
{
    int g = blockIdx.x * blockDim.x + threadIdx.x;
    int row = g >> 5, lane = g & 31;
    const float4* a4 = reinterpret_cast<const float4*>(A + (size_t)row * HFD);
    const float4* w4 = reinterpret_cast<const float4*>(w);
    float s = 0.f;
#pragma unroll
    for (int i = lane; i < HFD / 4; i += 32) {
        float4 a = a4[i], b = w4[i];
        s += a.x * b.x + a.y * b.y + a.z * b.z + a.w * b.w;
    }
#pragma unroll
    for (int o = 16; o; o >>= 1) s += __shfl_xor_sync(0xffffffffu, s, o);
    if (lane == 0) out[row] = s + bp[0];
}

// ---------------------------------------------------------------------------
// Loss: deterministic 2-stage sum of squared residuals.
// ---------------------------------------------------------------------------
template<bool BCAST>
__global__ void reduce_sq_k(const float* __restrict__ x, const float* __restrict__ mu,
                            size_t n, float* __restrict__ part)
{
    float s = 0.f;
    for (size_t i = (size_t)blockIdx.x * blockDim.x + threadIdx.x; i < n;
         i += (size_t)gridDim.x * blockDim.x) {
        float m = BCAST ? mu[i >> 5] : mu[i];
        float d = x[i] - m;
        s += d * d;
    }
    __shared__ float sm[256];
    sm[threadIdx.x] = s; __syncthreads();
    for (int o = 128; o; o >>= 1) {
        if (threadIdx.x < o) sm[threadIdx.x] += sm[threadIdx.x + o];
        __syncthreads();
    }
    if (threadIdx.x == 0) part[blockIdx.x] = sm[0];
}

__global__ void finalize_k(const float* __restrict__ part, float* __restrict__ out)
{
    __shared__ double sm[256];
    double s = 0.0;
    for (int i = threadIdx.x; i < 3 * NBLK; i += 256) s += (double)part[i];
    sm[threadIdx.x] = s; __syncthreads();
    for (int o = 128; o; o >>= 1) {
        if (threadIdx.x < o) sm[threadIdx.x] += sm[threadIdx.x + o];
        __syncthreads();
    }
    if (threadIdx.x == 0) {
        const double LOG2PI = 1.8378770664093453;
        out[0] = (float)(0.5 * sm[0] / (double)(TT * BB)
                         + 0.5 * LOG2PI * (double)(OBSD + 2 * ACTD));
    }
}

// ---------------------------------------------------------------------------
extern "C" void kernel_launch(void* const* d_in, const int* in_sizes, int n_in,
                              void* d_out, int out_size)
{
    const float* obs    = (const float*)d_in[0];
    const float* action = (const float*)d_in[1];
    /* d_in[2] reward: unused by the reference math */
    const float* w_ih = (const float*)d_in[3];
    const float* w_hh = (const float*)d_in[4];
    const float* b_ih = (const float*)d_in[5];
    const float* b_hh = (const float*)d_in[6];
    const float* ow0 = (const float*)d_in[7],  *ob0 = (const float*)d_in[8];
    const float* ow1 = (const float*)d_in[9],  *ob1 = (const float*)d_in[10];
    const float* ow2 = (const float*)d_in[11], *ob2 = (const float*)d_in[12];
    const float* aw0 = (const float*)d_in[13], *ab0 = (const float*)d_in[14];
    const float* aw1 = (const float*)d_in[15], *ab1 = (const float*)d_in[16];
    const float* aw2 = (const float*)d_in[17], *ab2 = (const float*)d_in[18];
    const float* rw0 = (const float*)d_in[19], *rb0 = (const float*)d_in[20];
    const float* rw1 = (const float*)d_in[21], *rb1 = (const float*)d_in[22];
    const float* rw2 = (const float*)d_in[23], *rb2 = (const float*)d_in[24];

    float *GI, *GI0, *HS, *P0, *P1, *PART;
    cudaGetSymbolAddress((void**)&GI,   g_GI);
    cudaGetSymbolAddress((void**)&GI0,  g_GI0);
    cudaGetSymbolAddress((void**)&HS,   g_HS);
    cudaGetSymbolAddress((void**)&P0,   g_P0);
    cudaGetSymbolAddress((void**)&P1,   g_P1);
    cudaGetSymbolAddress((void**)&PART, g_part);
    // MLP scratch aliases the (dead after the recurrence) GI buffer.
    float* F1 = GI;
    float* F2 = GI + TBn * HFD;

    float* out      = (float*)d_out;
    float* pre_obs  = out + 1;
    float* pre_act  = pre_obs + TBn * OBSD;
    float* pre_rew  = pre_act + TBn * ACTD;

    // rnn dynamic smem: 96KB W + 16KB A double buffer
    const int rnn_smem = (3 * 256 * 32 + 2 * 32 * 64) * (int)sizeof(float);
    cudaFuncSetAttribute(rnn_k, cudaFuncAttributeMaxDynamicSharedMemorySize, rnn_smem);

    // 1) GI = [obs‖action] @ w_ih^T + b_ih   for all T*B rows
    sgemm_k<128, 128, 8, 8, 8, 0, true><<<dim3(G3D / 128, TBn / 128), 256>>>(
        obs, 0, action, w_ih, IND, b_ih, GI, G3D, IND);

    // 2) GI0 = obs[0] @ w_ih[:, :128]^T + b_ih  (action part of x0 is zero)
    sgemm_k<64, 64, 8, 4, 4, 0, false><<<dim3(G3D / 64, BB / 64), 256>>>(
        obs, OBSD, nullptr, w_ih, IND, b_ih, GI0, G3D, OBSD);

    // 3) h0 -> HS[0]  (also zeroes rnn sync counters)
    gate0_k<<<(BB * HIDD) / 256, 256>>>(GI0, b_hh, HS);

    // 4) recurrence: ONE persistent kernel, K-split, all 511 steps
    rnn_k<<<RNCTA, 256, rnn_smem>>>(w_hh, b_hh, GI, HS, P0, P1);

    dim3 gH(HFD / 128, TBn / 128);
    dim3 gO(OBSD / 128, TBn / 128);
    dim3 gA(ACTD / 32, TBn / 128);

    // 5) obs head
    sgemm_k<128, 128, 8, 8, 8, 1, false><<<gH, 256>>>(HS, HIDD, nullptr, ow0, HIDD, ob0, F1, HFD, HIDD);
    sgemm_k<128, 128, 8, 8, 8, 1, false><<<gH, 256>>>(F1, HFD, nullptr, ow1, HFD, ob1, F2, HFD, HFD);
    sgemm_k<128, 128, 8, 8, 8, 0, false><<<gO, 256>>>(F2, HFD, nullptr, ow2, HFD, ob2, pre_obs, OBSD, HFD);

    // 6) action head
    sgemm_k<128, 128, 8, 8, 8, 1, false><<<gH, 256>>>(HS, HIDD, nullptr, aw0, HIDD, ab0, F1, HFD, HIDD);
    sgemm_k<128, 128, 8, 8, 8, 1, false><<<gH, 256>>>(F1, HFD, nullptr, aw1, HFD, ab1, F2, HFD, HFD);
    sgemm_k<128, 32, 8, 8, 4, 0, false><<<gA, 128>>>(F2, HFD, nullptr, aw2, HFD, ab2, pre_act, ACTD, HFD);

    // 7) reward head
    sgemm_k<128, 128, 8, 8, 8, 1, false><<<gH, 256>>>(HS, HIDD, nullptr, rw0, HIDD, rb0, F1, HFD, HIDD);
    sgemm_k<128, 128, 8, 8, 8, 1, false><<<gH, 256>>>(F1, HFD, nullptr, rw1, HFD, rb1, F2, HFD, HFD);
    dot_k<<<TBn / 8, 256>>>(F2, rw2, rb2, pre_rew);

    // 8) losses (reward_loss faithfully reproduces the broadcast-vs-action bug)
    reduce_sq_k<false><<<NBLK, 256>>>(obs,    pre_obs, TBn * OBSD, PART);
    reduce_sq_k<false><<<NBLK, 256>>>(action, pre_act, TBn * ACTD, PART + NBLK);
    reduce_sq_k<true ><<<NBLK, 256>>>(action, pre_rew, TBn * ACTD, PART + 2 * NBLK);
    finalize_k<<<1, 256>>>(PART, out);
}

// round 14
// speedup vs baseline: 1.7340x; 1.2147x over previous
#include <cuda_runtime.h>
#include <math.h>

// Problem dims
#define TT   512
#define BB   256
#define OBSD 128
#define ACTD 32
#define IND  160
#define HIDD 512
#define G3D  1536
#define HFD  512

static constexpr size_t TBn = (size_t)TT * BB;      // 131072
static constexpr int NBLK = 2048;                    // reduction blocks per sum

// -------- scratch (static device globals; no runtime allocation) ----------
__device__ float g_GI [TBn * G3D];   // [T*B, 1536] input-gate preacts
__device__ float g_GI0[BB  * G3D];   // step-0 preacts
__device__ float g_HS [TBn * HIDD];  // emitted hidden states
__device__ float g_part[3 * NBLK];   // loss partials

// monotonic barrier counter (zeroed by gate0_k each call -> graph-replay safe)
__device__ unsigned g_rcnt;

__device__ __forceinline__ float4 ldg4(const float* p) {
    return *reinterpret_cast<const float4*>(p);
}
__device__ __forceinline__ float sigmoidf_(float x) { return 1.f / (1.f + expf(-x)); }

// ---- packed fp32x2 helpers ----
__device__ __forceinline__ unsigned long long pk2(float lo, float hi) {
    unsigned long long r;
    asm("mov.b64 %0, {%1, %2};" : "=l"(r) : "f"(lo), "f"(hi));
    return r;
}
__device__ __forceinline__ void fma2(unsigned long long& d,
                                     unsigned long long a, unsigned long long b) {
    asm("fma.rn.f32x2 %0, %1, %2, %0;" : "+l"(d) : "l"(a), "l"(b));
}
__device__ __forceinline__ float2 upk2(unsigned long long v) {
    float2 f;
    asm("mov.b64 {%0, %1}, %2;" : "=f"(f.x), "=f"(f.y) : "l"(v));
    return f;
}

// ---------------------------------------------------------------------------
// Generic tiled SGEMM with f32x2 inner loop (measured at the fp32 roofline).
// ---------------------------------------------------------------------------
template<int BM, int BN, int BK, int TM, int TN, int ACTMODE, bool CONCAT>
__global__ void __launch_bounds__((BM / TM) * (BN / TN))
sgemm_k(const float* __restrict__ A, int ldA,
        const float* __restrict__ A2,
        const float* __restrict__ W, int ldW,
        const float* __restrict__ bias,
        float* __restrict__ C, int ldC,
        int K)
{
    constexpr int NT = (BM / TM) * (BN / TN);
    constexpr int KQ = BK / 4;
    constexpr int TNP = TN / 2;

    __shared__ __align__(16) float As[BK][BM + 4];
    __shared__ __align__(16) float Ws[BK][BN + 4];

    const int tid = threadIdx.x;
    const int tx  = tid % (BN / TN);
    const int ty  = tid / (BN / TN);
    const int m0  = blockIdx.y * BM;
    const int n0  = blockIdx.x * BN;

    unsigned long long acc2[TM][TNP];
#pragma unroll
    for (int i = 0; i < TM; i++)
#pragma unroll
        for (int j = 0; j < TNP; j++) acc2[i][j] = 0ull;

    for (int k0 = 0; k0 < K; k0 += BK) {
        for (int i4 = tid; i4 < BM * KQ; i4 += NT) {
            int m = i4 / KQ, q = i4 % KQ;
            int kg = k0 + q * 4;
            float4 v;
            if (CONCAT) {
                if (kg < OBSD) v = ldg4(A  + (size_t)(m0 + m) * OBSD + kg);
                else           v = ldg4(A2 + (size_t)(m0 + m) * ACTD + (kg - OBSD));
            } else {
                v = ldg4(A + (size_t)(m0 + m) * ldA + kg);
            }
            As[q * 4 + 0][m] = v.x; As[q * 4 + 1][m] = v.y;
            As[q * 4 + 2][m] = v.z; As[q * 4 + 3][m] = v.w;
        }
        for (int i4 = tid; i4 < BN * KQ; i4 += NT) {
            int n = i4 / KQ, q = i4 % KQ;
            int kg = k0 + q * 4;
            float4 v = ldg4(W + (size_t)(n0 + n) * ldW + kg);
            Ws[q * 4 + 0][n] = v.x; Ws[q * 4 + 1][n] = v.y;
            Ws[q * 4 + 2][n] = v.z; Ws[q * 4 + 3][n] = v.w;
        }
        __syncthreads();

#pragma unroll
        for (int kk = 0; kk < BK; kk++) {
            float a[TM];
#pragma unroll
            for (int i = 0; i < TM; i += 4)
                *reinterpret_cast<float4*>(&a[i]) =
                    *reinterpret_cast<const float4*>(&As[kk][ty * TM + i]);
            unsigned long long b2[TNP];
#pragma unroll
            for (int j = 0; j < TNP; j += 2) {
                ulonglong2 t = *reinterpret_cast<const ulonglong2*>(&Ws[kk][tx * TN + 2 * j]);
                b2[j] = t.x; b2[j + 1] = t.y;
            }
#pragma unroll
            for (int i = 0; i < TM; i++) {
                unsigned long long ad = pk2(a[i], a[i]);
#pragma unroll
                for (int j = 0; j < TNP; j++) fma2(acc2[i][j], ad, b2[j]);
            }
        }
        __syncthreads();
    }

#pragma unroll
    for (int i = 0; i < TM; i++) {
        size_t m = (size_t)m0 + ty * TM + i;
#pragma unroll
        for (int j = 0; j < TNP; j++) {
            float2 v2 = upk2(acc2[i][j]);
            int n = n0 + tx * TN + 2 * j;
            float v = v2.x + bias[n];
            float w = v2.y + bias[n + 1];
            if (ACTMODE == 1) {
                v = (v > 0.f) ? v : expm1f(v);
                w = (w > 0.f) ? w : expm1f(w);
            }
            C[m * (size_t)ldC + n]     = v;
            C[m * (size_t)ldC + n + 1] = w;
        }
    }
}

// ---------------------------------------------------------------------------
// Persistent GRU recurrence v5: v4's fat-thread inner loop on R8's proven
// slice geometry (112KB smem, the footprint class that has passed 3x).
// 128 CTAs x 128 threads (1 CTA/SM).
//   CTA: bg=blockIdx.x>>5 (4 x 64 rows), cg=blockIdx.x&31 (32 x 16 cols).
//   W slice [3][512][16] = 96KB in smem for the whole kernel; h_t staged in
//   double-buffered 32-k chunks (2 x 8KB).
// Thread tile: 4 rows x 2 cols x 3 gates = 12 FFMA2 per (1 LDS.128 + 3
// LDS.64).  Gate math applied directly on the accumulators (no partials).
// ONE monotonic grid barrier per step (R11-proven), nanosleep poll.
// ---------------------------------------------------------------------------
#define RNCTA 128

__device__ __forceinline__ void rnn_load_chunk(float* __restrict__ dst,
                                               const float* __restrict__ hp,
                                               int b0, int c, int tid)
{
#pragma unroll
    for (int p = 0; p < 4; p++) {
        int u = p * 128 + tid;
        int row = u & 63, q = u >> 6;                 // 64 rows x 8 float4
        float4 v = ldg4(hp + (size_t)(b0 + row) * HIDD + c * 32 + q * 4);
        dst[(q * 4 + 0) * 64 + row] = v.x;
        dst[(q * 4 + 1) * 64 + row] = v.y;
        dst[(q * 4 + 2) * 64 + row] = v.z;
        dst[(q * 4 + 3) * 64 + row] = v.w;
    }
}

__global__ void __launch_bounds__(128)
rnn_k(const float* __restrict__ w_hh, const float* __restrict__ b_hh,
      const float* __restrict__ gi_all, float* __restrict__ hs)
{
    extern __shared__ float sm[];
    float* Wsm  = sm;                    // [3][512][16] = 24576 floats (96KB)
    float* Abuf = sm + 3 * 512 * 16;     // 2 x [32k][64row] = 4096 floats (16KB)

    const int tid = threadIdx.x;
    const int bg  = blockIdx.x >> 5;     // 4 groups x 64 rows
    const int cg  = blockIdx.x & 31;     // 32 groups x 16 cols
    const int b0  = bg * 64;
    const int j0  = cg * 16;
    const int tx  = tid & 7;             // 8 col-pairs (16 cols)
    const int ty  = tid >> 3;            // 16 row-quads (64 rows)

    // one-time: W slice -> smem as [g][k][col] (16-col rows)
    for (int u = tid; u < 3 * 16 * 128; u += 128) {
        int g   = u >> 11;               // 0..2
        int r   = u & 2047;
        int col = r >> 7;                // 0..15
        int kq  = r & 127;               // k = 4*kq
        float4 v = ldg4(w_hh + (size_t)(g * HIDD + j0 + col) * HIDD + kq * 4);
        Wsm[(g * 512 + kq * 4 + 0) * 16 + col] = v.x;
        Wsm[(g * 512 + kq * 4 + 1) * 16 + col] = v.y;
        Wsm[(g * 512 + kq * 4 + 2) * 16 + col] = v.z;
        Wsm[(g * 512 + kq * 4 + 3) * 16 + col] = v.w;
    }
    const int jg = j0 + 2 * tx;
    const float2 br = *reinterpret_cast<const float2*>(b_hh + jg);
    const float2 bz = *reinterpret_cast<const float2*>(b_hh + 512 + jg);
    const float2 bn = *reinterpret_cast<const float2*>(b_hh + 1024 + jg);
    __syncthreads();

    for (int t = 0; t < TT - 1; t++) {
        const float* hp = hs + (size_t)t * BB * HIDD;
        float*       ho = hs + (size_t)(t + 1) * BB * HIDD;
        const float* gi = gi_all + (size_t)t * BB * G3D;

        // prefetch gate-phase operands for this thread's 4 rows x 2 cols
        float2 gr_[4], gz_[4], gn_[4], hp_[4];
#pragma unroll
        for (int i = 0; i < 4; i++) {
            const float* gim = gi + (size_t)(b0 + 4 * ty + i) * G3D;
            gr_[i] = *reinterpret_cast<const float2*>(gim + jg);
            gz_[i] = *reinterpret_cast<const float2*>(gim + 512 + jg);
            gn_[i] = *reinterpret_cast<const float2*>(gim + 1024 + jg);
            hp_[i] = *reinterpret_cast<const float2*>(
                hp + (size_t)(b0 + 4 * ty + i) * HIDD + jg);
        }

        unsigned long long aR[4] = {0,0,0,0}, aZ[4] = {0,0,0,0}, aN[4] = {0,0,0,0};

        rnn_load_chunk(Abuf, hp, b0, 0, tid);
        __syncthreads();
#pragma unroll 1
        for (int c = 0; c < 16; c++) {
            const float* Ac = Abuf + (c & 1) * 2048;
            if (c < 15) rnn_load_chunk(Abuf + ((c + 1) & 1) * 2048, hp, b0, c + 1, tid);
            const float* wR = &Wsm[(0 * 512 + c * 32) * 16 + 2 * tx];
            const float* wZ = &Wsm[(1 * 512 + c * 32) * 16 + 2 * tx];
            const float* wN = &Wsm[(2 * 512 + c * 32) * 16 + 2 * tx];
            const float* Ab = &Ac[4 * ty];
#pragma unroll
            for (int kk = 0; kk < 32; kk++) {
                float4 a4 = *reinterpret_cast<const float4*>(Ab + kk * 64);
                unsigned long long r2 = *reinterpret_cast<const unsigned long long*>(wR + kk * 16);
                unsigned long long z2 = *reinterpret_cast<const unsigned long long*>(wZ + kk * 16);
                unsigned long long n2 = *reinterpret_cast<const unsigned long long*>(wN + kk * 16);
                unsigned long long a0 = pk2(a4.x, a4.x);
                unsigned long long a1 = pk2(a4.y, a4.y);
                unsigned long long a2 = pk2(a4.z, a4.z);
                unsigned long long a3 = pk2(a4.w, a4.w);
                fma2(aR[0], a0, r2); fma2(aR[1], a1, r2);
                fma2(aR[2], a2, r2); fma2(aR[3], a3, r2);
                fma2(aZ[0], a0, z2); fma2(aZ[1], a1, z2);
                fma2(aZ[2], a2, z2); fma2(aZ[3], a3, z2);
                fma2(aN[0], a0, n2); fma2(aN[1], a1, n2);
                fma2(aN[2], a2, n2); fma2(aN[3], a3, n2);
            }
            __syncthreads();
        }

        // gate math directly on accumulators; store 4 x float2 of h_{t+1}
#pragma unroll
        for (int i = 0; i < 4; i++) {
            float2 vr = upk2(aR[i]), vz = upk2(aZ[i]), vn = upk2(aN[i]);
            float r0 = sigmoidf_(gr_[i].x + vr.x + br.x);
            float r1 = sigmoidf_(gr_[i].y + vr.y + br.y);
            float z0 = sigmoidf_(gz_[i].x + vz.x + bz.x);
            float z1 = sigmoidf_(gz_[i].y + vz.y + bz.y);
            float n0 = tanhf    (gn_[i].x + r0 * (vn.x + bn.x));
            float n1 = tanhf    (gn_[i].y + r1 * (vn.y + bn.y));
            float2 hv;
            hv.x = (1.f - z0) * n0 + z0 * hp_[i].x;
            hv.y = (1.f - z1) * n1 + z1 * hp_[i].y;
            *reinterpret_cast<float2*>(
                ho + (size_t)(b0 + 4 * ty + i) * HIDD + jg) = hv;
        }

        // ---- ONE grid barrier per step (monotonic target; nanosleep poll) ----
        __threadfence();
        __syncthreads();
        if (tid == 0) {
            atomicAdd(&g_rcnt, 1u);
            const unsigned target = (unsigned)(RNCTA * (t + 1));
            while (*(volatile unsigned*)&g_rcnt < target) __nanosleep(20);
        }
        __syncthreads();
    }
}

// step 0: h_prev = 0  =>  gh = b_hh,  h0 = (1-z)*n.  Also zeroes the rnn
// barrier counter (runs before rnn_k every call -> graph-replay safe).
__global__ void gate0_k(const float* __restrict__ gi, const float* __restrict__ bhh,
                        float* __restrict__ ho)
{
    if (blockIdx.x == 0 && threadIdx.x == 0) {
        g_rcnt = 0u;
        __threadfence();
    }
    int idx = blockIdx.x * blockDim.x + threadIdx.x;
    int b = idx >> 9, j = idx & 511;
    size_t base = (size_t)b * G3D + j;
    float r = sigmoidf_(gi[base]        + bhh[j]);
    float z = sigmoidf_(gi[base + 512]  + bhh[512 + j]);
    float n = tanhf    (gi[base + 1024] + r * bhh[1024 + j]);
    ho[idx] = (1.f - z) * n;
}

// ---------------------------------------------------------------------------
// N=1 head: one warp per row.
// ---------------------------------------------------------------------------
__global__ void dot_k(const float* __restrict__ A, const float* __restrict__ w,
                      const float* __restrict__ bp, float* __restrict__ out)
{
    int g = blockIdx.x * blockDim.x + threadIdx.x;
    int row = g >> 5, lane = g & 31;
    const float4* a4 = reinterpret_cast<const float4*>(A + (size_t)row * HFD);
    const float4* w4 = reinterpret_cast<const float4*>(w);
    float s = 0.f;
#pragma unroll
    for (int i = lane; i < HFD / 4; i += 32) {
        float4 a = a4[i], b = w4[i];
        s += a.x * b.x + a.y * b.y + a.z * b.z + a.w * b.w;
    }
#pragma unroll
    for (int o = 16; o; o >>= 1) s += __shfl_xor_sync(0xffffffffu, s, o);
    if (lane == 0) out[row] = s + bp[0];
}

// ---------------------------------------------------------------------------
// Loss: deterministic 2-stage sum of squared residuals.
// ---------------------------------------------------------------------------
template<bool BCAST>
__global__ void reduce_sq_k(const float* __restrict__ x, const float* __restrict__ mu,
                            size_t n, float* __restrict__ part)
{
    float s = 0.f;
    for (size_t i = (size_t)blockIdx.x * blockDim.x + threadIdx.x; i < n;
         i += (size_t)gridDim.x * blockDim.x) {
        float m = BCAST ? mu[i >> 5] : mu[i];
        float d = x[i] - m;
        s += d * d;
    }
    __shared__ float sm[256];
    sm[threadIdx.x] = s; __syncthreads();
    for (int o = 128; o; o >>= 1) {
        if (threadIdx.x < o) sm[threadIdx.x] += sm[threadIdx.x + o];
        __syncthreads();
    }
    if (threadIdx.x == 0) part[blockIdx.x] = sm[0];
}

__global__ void finalize_k(const float* __restrict__ part, float* __restrict__ out)
{
    __shared__ double sm[256];
    double s = 0.0;
    for (int i = threadIdx.x; i < 3 * NBLK; i += 256) s += (double)part[i];
    sm[threadIdx.x] = s; __syncthreads();
    for (int o = 128; o; o >>= 1) {
        if (threadIdx.x < o) sm[threadIdx.x] += sm[threadIdx.x + o];
        __syncthreads();
    }
    if (threadIdx.x == 0) {
        const double LOG2PI = 1.8378770664093453;
        out[0] = (float)(0.5 * sm[0] / (double)(TT * BB)
                         + 0.5 * LOG2PI * (double)(OBSD + 2 * ACTD));
    }
}

// ---------------------------------------------------------------------------
extern "C" void kernel_launch(void* const* d_in, const int* in_sizes, int n_in,
                              void* d_out, int out_size)
{
    const float* obs    = (const float*)d_in[0];
    const float* action = (const float*)d_in[1];
    /* d_in[2] reward: unused by the reference math */
    const float* w_ih = (const float*)d_in[3];
    const float* w_hh = (const float*)d_in[4];
    const float* b_ih = (const float*)d_in[5];
    const float* b_hh = (const float*)d_in[6];
    const float* ow0 = (const float*)d_in[7],  *ob0 = (const float*)d_in[8];
    const float* ow1 = (const float*)d_in[9],  *ob1 = (const float*)d_in[10];
    const float* ow2 = (const float*)d_in[11], *ob2 = (const float*)d_in[12];
    const float* aw0 = (const float*)d_in[13], *ab0 = (const float*)d_in[14];
    const float* aw1 = (const float*)d_in[15], *ab1 = (const float*)d_in[16];
    const float* aw2 = (const float*)d_in[17], *ab2 = (const float*)d_in[18];
    const float* rw0 = (const float*)d_in[19], *rb0 = (const float*)d_in[20];
    const float* rw1 = (const float*)d_in[21], *rb1 = (const float*)d_in[22];
    const float* rw2 = (const float*)d_in[23], *rb2 = (const float*)d_in[24];

    float *GI, *GI0, *HS, *PART;
    cudaGetSymbolAddress((void**)&GI,   g_GI);
    cudaGetSymbolAddress((void**)&GI0,  g_GI0);
    cudaGetSymbolAddress((void**)&HS,   g_HS);
    cudaGetSymbolAddress((void**)&PART, g_part);
    // MLP scratch aliases the (dead after the recurrence) GI buffer.
    float* F1 = GI;
    float* F2 = GI + TBn * HFD;

    float* out      = (float*)d_out;
    float* pre_obs  = out + 1;
    float* pre_act  = pre_obs + TBn * OBSD;
    float* pre_rew  = pre_act + TBn * ACTD;

    // rnn dynamic smem: 96KB W + 16KB A double buffer = 112KB
    const int rnn_smem = (3 * 512 * 16 + 2 * 32 * 64) * (int)sizeof(float);
    cudaFuncSetAttribute(rnn_k, cudaFuncAttributeMaxDynamicSharedMemorySize, rnn_smem);

    // 1) GI = [obs‖action] @ w_ih^T + b_ih   for all T*B rows
    sgemm_k<128, 128, 8, 8, 8, 0, true><<<dim3(G3D / 128, TBn / 128), 256>>>(
        obs, 0, action, w_ih, IND, b_ih, GI, G3D, IND);

    // 2) GI0 = obs[0] @ w_ih[:, :128]^T + b_ih  (action part of x0 is zero)
    sgemm_k<64, 64, 8, 4, 4, 0, false><<<dim3(G3D / 64, BB / 64), 256>>>(
        obs, OBSD, nullptr, w_ih, IND, b_ih, GI0, G3D, OBSD);

    // 3) h0 -> HS[0]  (also zeroes the rnn barrier counter)
    gate0_k<<<(BB * HIDD) / 256, 256>>>(GI0, b_hh, HS);

    // 4) recurrence: ONE persistent kernel, full-K slices, all 511 steps
    rnn_k<<<RNCTA, 128, rnn_smem>>>(w_hh, b_hh, GI, HS);

    dim3 gH(HFD / 128, TBn / 128);
    dim3 gO(OBSD / 128, TBn / 128);
    dim3 gA(ACTD / 32, TBn / 128);

    // 5) obs head
    sgemm_k<128, 128, 8, 8, 8, 1, false><<<gH, 256>>>(HS, HIDD, nullptr, ow0, HIDD, ob0, F1, HFD, HIDD);
    sgemm_k<128, 128, 8, 8, 8, 1, false><<<gH, 256>>>(F1, HFD, nullptr, ow1, HFD, ob1, F2, HFD, HFD);
    sgemm_k<128, 128, 8, 8, 8, 0, false><<<gO, 256>>>(F2, HFD, nullptr, ow2, HFD, ob2, pre_obs, OBSD, HFD);

    // 6) action head
    sgemm_k<128, 128, 8, 8, 8, 1, false><<<gH, 256>>>(HS, HIDD, nullptr, aw0, HIDD, ab0, F1, HFD, HIDD);
    sgemm_k<128, 128, 8, 8, 8, 1, false><<<gH, 256>>>(F1, HFD, nullptr, aw1, HFD, ab1, F2, HFD, HFD);
    sgemm_k<128, 32, 8, 8, 4, 0, false><<<gA, 128>>>(F2, HFD, nullptr, aw2, HFD, ab2, pre_act, ACTD, HFD);

    // 7) reward head
    sgemm_k<128, 128, 8, 8, 8, 1, false><<<gH, 256>>>(HS, HIDD, nullptr, rw0, HIDD, rb0, F1, HFD, HIDD);
    sgemm_k<128, 128, 8, 8, 8, 1, false><<<gH, 256>>>(F1, HFD, nullptr, rw1, HFD, rb1, F2, HFD, HFD);
    dot_k<<<TBn / 8, 256>>>(F2, rw2, rb2, pre_rew);

    // 8) losses (reward_loss faithfully reproduces the broadcast-vs-action bug)
    reduce_sq_k<false><<<NBLK, 256>>>(obs,    pre_obs, TBn * OBSD, PART);
    reduce_sq_k<false><<<NBLK, 256>>>(action, pre_act, TBn * ACTD, PART + NBLK);
    reduce_sq_k<true ><<<NBLK, 256>>>(action, pre_rew, TBn * ACTD, PART + 2 * NBLK);
    finalize_k<<<1, 256>>>(PART, out);
}